// round 2
// baseline (speedup 1.0000x reference)
#include <cuda_runtime.h>
#include <math.h>

#define EPSV 1e-5f
#define HW   65536
#define CCH  64
#define NB   8
#define TP   128

// ---------------- scratch (device globals; no runtime allocation) ----------
__device__ float    g_sumx[2*NB*CCH];
__device__ unsigned g_cmax[2*NB*CCH];
__device__ unsigned g_kmax[2*NB];
__device__ float    g_klog[2*NB*HW];     // 4 MB
__device__ float    g_fea [2*NB*CCH];
__device__ float    g_Z   [2*NB];
__device__ float    g_avg [2*NB*CCH];
__device__ float    g_msm [2*NB*CCH];
__device__ float    g_gate[2*NB*CCH];
__device__ float    g_half[2*NB*HW];     // 4 MB
__device__ float    g_keywf[CCH];
__device__ float    g_valwf[CCH*CCH];
__device__ float    g_valoff[CCH];
__device__ float    g_sc[4];             // keyoff, hw0, hw1, hoff

// ordered-int encoding for float atomicMax
__device__ __forceinline__ unsigned ordf(float f) {
    unsigned u = __float_as_uint(f);
    return (u & 0x80000000u) ? ~u : (u | 0x80000000u);
}
__device__ __forceinline__ float deord(unsigned u) {
    u = (u & 0x80000000u) ? (u & 0x7fffffffu) : ~u;
    return __uint_as_float(u);
}
__device__ __forceinline__ float siluf(float z) { return z / (1.f + expf(-z)); }

// ---------------- init: zero accumulators + fold BN into weights ----------
__global__ void k_init(const float* key_w, const float* key_g, const float* key_b,
                       const float* key_m, const float* key_v,
                       const float* val_w, const float* val_g, const float* val_b,
                       const float* val_m, const float* val_v,
                       const float* half_w, const float* half_g, const float* half_b,
                       const float* half_m, const float* half_v) {
    int t = threadIdx.x;
    for (int i = t; i < 2*NB*CCH; i += blockDim.x) { g_sumx[i] = 0.f; g_cmax[i] = 0u; g_fea[i] = 0.f; }
    for (int i = t; i < 2*NB; i += blockDim.x) { g_kmax[i] = 0u; g_Z[i] = 0.f; }
    if (t < CCH) {
        float ks = key_g[0] * rsqrtf(key_v[0] + EPSV);
        g_keywf[t] = key_w[t] * ks;
        float vs = val_g[t] * rsqrtf(val_v[t] + EPSV);
        g_valoff[t] = val_b[t] - val_m[t] * vs;
        for (int c = 0; c < CCH; c++) g_valwf[t*CCH + c] = val_w[t*CCH + c] * vs;
        if (t == 0) g_sc[0] = key_b[0] - key_m[0] * ks;
        if (t == 1) {
            float hs = half_g[0] * rsqrtf(half_v[0] + EPSV);
            g_sc[1] = half_w[0] * hs;
            g_sc[2] = half_w[1] * hs;
            g_sc[3] = half_b[0] - half_m[0] * hs;
        }
    }
}

// ---------------- pass1: conv_w GEMM -> channel max; x sums; key logits ----
__global__ void __launch_bounds__(128)
k_pass1(const float* __restrict__ xr, const float* __restrict__ xi,
        const float* __restrict__ conv_w) {
    extern __shared__ float sm[];
    float* Xs  = sm;             // 64*128
    float* Ws  = sm + 8192;      // 64*65 (padded)
    float* kw  = Ws + 4160;      // 64
    float* red = kw + 64;        // 32
    int s = blockIdx.z, n = blockIdx.y;
    int p0 = blockIdx.x * TP;
    const float* x = (s == 0 ? xr : xi) + (size_t)n * CCH * HW + p0;
    int t = threadIdx.x;

    for (int i4 = t; i4 < 2048; i4 += 128) {
        int c = i4 >> 5, pq = i4 & 31;
        *(float4*)(Xs + c*TP + pq*4) = *(const float4*)(x + (size_t)c*HW + pq*4);
    }
    for (int i = t; i < 4096; i += 128) Ws[(i >> 6)*65 + (i & 63)] = conv_w[i];
    if (t < 64) kw[t] = g_keywf[t];
    __syncthreads();

    int og = t >> 4, pg = t & 15;
    float acc[8][8];
    #pragma unroll
    for (int i = 0; i < 8; i++)
        #pragma unroll
        for (int j = 0; j < 8; j++) acc[i][j] = 0.f;

    #pragma unroll 4
    for (int c = 0; c < 64; c++) {
        float wv[8], xv[8];
        #pragma unroll
        for (int i = 0; i < 8; i++) wv[i] = Ws[(og + 8*i)*65 + c];
        #pragma unroll
        for (int j = 0; j < 8; j++) xv[j] = Xs[c*TP + pg + 16*j];
        #pragma unroll
        for (int i = 0; i < 8; i++)
            #pragma unroll
            for (int j = 0; j < 8; j++) acc[i][j] = fmaf(wv[i], xv[j], acc[i][j]);
    }

    int base = (s*NB + n) * CCH;
    // per-channel max over pixels (bias added later; max(dot)+b == max(dot+b))
    #pragma unroll
    for (int i = 0; i < 8; i++) {
        float m = acc[i][0];
        #pragma unroll
        for (int j = 1; j < 8; j++) m = fmaxf(m, acc[i][j]);
        #pragma unroll
        for (int k = 8; k >= 1; k >>= 1) m = fmaxf(m, __shfl_xor_sync(0xffffffffu, m, k));
        if (pg == 0) atomicMax(&g_cmax[base + og + 8*i], ordf(m));
    }
    // per-channel sums of x (for exact mean path)
    #pragma unroll
    for (int i = 0; i < 8; i++) {
        int c = og*8 + i;
        float ssum = 0.f;
        #pragma unroll
        for (int j = 0; j < 8; j++) ssum += Xs[c*TP + pg + 16*j];
        #pragma unroll
        for (int k = 8; k >= 1; k >>= 1) ssum += __shfl_xor_sync(0xffffffffu, ssum, k);
        if (pg == 0) atomicAdd(&g_sumx[base + c], ssum);
    }
    // key logit for pixel t
    float z = g_sc[0];
    #pragma unroll 8
    for (int c = 0; c < 64; c++) z = fmaf(kw[c], Xs[c*TP + t], z);
    float kl = siluf(z);
    g_klog[(size_t)(s*NB + n) * HW + p0 + t] = kl;
    float km = kl;
    #pragma unroll
    for (int k = 16; k >= 1; k >>= 1) km = fmaxf(km, __shfl_xor_sync(0xffffffffu, km, k));
    if ((t & 31) == 0) red[t >> 5] = km;
    __syncthreads();
    if (t == 0) {
        km = fmaxf(fmaxf(red[0], red[1]), fmaxf(red[2], red[3]));
        atomicMax(&g_kmax[s*NB + n], ordf(km));
    }
}

// ---------------- mid: channel softmaxes (avg from sums, max from cmax) ----
__device__ __forceinline__ float blockmax64(float v, float* tmp) {
    tmp[threadIdx.x] = v; __syncthreads();
    for (int k = 32; k >= 1; k >>= 1) {
        if (threadIdx.x < k) tmp[threadIdx.x] = fmaxf(tmp[threadIdx.x], tmp[threadIdx.x + k]);
        __syncthreads();
    }
    float r = tmp[0]; __syncthreads(); return r;
}
__device__ __forceinline__ float blocksum64(float v, float* tmp) {
    tmp[threadIdx.x] = v; __syncthreads();
    for (int k = 32; k >= 1; k >>= 1) {
        if (threadIdx.x < k) tmp[threadIdx.x] += tmp[threadIdx.x + k];
        __syncthreads();
    }
    float r = tmp[0]; __syncthreads(); return r;
}

__global__ void k_mid(const float* __restrict__ conv_w, const float* __restrict__ conv_b) {
    int s = blockIdx.x, n = blockIdx.y, o = threadIdx.x;
    __shared__ float sx[64], tmp[64];
    int base = (s*NB + n) * CCH;
    sx[o] = g_sumx[base + o] * (1.f / (float)HW);
    __syncthreads();
    float mean = conv_b[o];
    for (int c = 0; c < 64; c++) mean = fmaf(sx[c], conv_w[o*64 + c], mean);
    float mx = deord(g_cmax[base + o]) + conv_b[o];

    float m1 = blockmax64(mean, tmp);
    float e1 = expf(mean - m1);
    float s1 = blocksum64(e1, tmp);
    g_avg[base + o] = e1 / s1;

    float m2 = blockmax64(mx, tmp);
    float e2 = expf(mx - m2);
    float s2 = blocksum64(e2, tmp);
    g_msm[base + o] = e2 / s2;
}

// ---------------- pass2: val GEMM + fused fea/Z/half -----------------------
__global__ void __launch_bounds__(128)
k_pass2(const float* __restrict__ xr, const float* __restrict__ xi) {
    extern __shared__ float sm[];
    float* Xs   = sm;            // 8192, reused as Vs after GEMM
    float* Ws   = sm + 8192;     // 4160
    float* voff = Ws + 4160;     // 64
    float* av   = voff + 64;     // 64
    float* mv   = av + 64;       // 64
    float* es   = mv + 64;       // 128
    float* red  = es + 128;      // 32
    int sx = blockIdx.z, n = blockIdx.y, so = 1 - sx;   // v from side sx feeds output side so
    int p0 = blockIdx.x * TP;
    int t = threadIdx.x;
    const float* x = (sx == 0 ? xr : xi) + (size_t)n * CCH * HW + p0;

    for (int i4 = t; i4 < 2048; i4 += 128) {
        int c = i4 >> 5, pq = i4 & 31;
        *(float4*)(Xs + c*TP + pq*4) = *(const float4*)(x + (size_t)c*HW + pq*4);
    }
    for (int i = t; i < 4096; i += 128) Ws[(i >> 6)*65 + (i & 63)] = g_valwf[i];
    if (t < 64) {
        voff[t] = g_valoff[t];
        int b2 = (so*NB + n) * CCH;
        av[t] = g_avg[b2 + t];
        mv[t] = g_msm[b2 + t];
    }
    __syncthreads();

    int og = t >> 4, pg = t & 15;
    float acc[8][8];
    #pragma unroll
    for (int i = 0; i < 8; i++)
        #pragma unroll
        for (int j = 0; j < 8; j++) acc[i][j] = 0.f;

    #pragma unroll 4
    for (int c = 0; c < 64; c++) {
        float wv[8], xv[8];
        #pragma unroll
        for (int i = 0; i < 8; i++) wv[i] = Ws[(og + 8*i)*65 + c];
        #pragma unroll
        for (int j = 0; j < 8; j++) xv[j] = Xs[c*TP + pg + 16*j];
        #pragma unroll
        for (int i = 0; i < 8; i++)
            #pragma unroll
            for (int j = 0; j < 8; j++) acc[i][j] = fmaf(wv[i], xv[j], acc[i][j]);
    }
    __syncthreads();   // done reading Xs, about to overwrite with V

    #pragma unroll
    for (int i = 0; i < 8; i++) {
        float off = voff[og + 8*i];
        #pragma unroll
        for (int j = 0; j < 8; j++)
            Xs[(og + 8*i)*TP + pg + 16*j] = siluf(acc[i][j] + off);
    }
    __syncthreads();

    // per-pixel: key weight e, half output
    float kmaxv = deord(g_kmax[so*NB + n]);
    float kl = g_klog[(size_t)(so*NB + n) * HW + p0 + t];
    float e = expf(kl - kmaxv);
    es[t] = e;
    float sa = 0.f, smx = 0.f;
    #pragma unroll 8
    for (int c = 0; c < 64; c++) {
        float vv = Xs[c*TP + t];
        sa  = fmaf(av[c], vv, sa);
        smx = fmaf(mv[c], vv, smx);
    }
    float pre = g_sc[1]*sa + g_sc[2]*smx + g_sc[3];
    g_half[(size_t)(so*NB + n) * HW + p0 + t] = siluf(pre);

    float zs = e;
    #pragma unroll
    for (int k = 16; k >= 1; k >>= 1) zs += __shfl_xor_sync(0xffffffffu, zs, k);
    if ((t & 31) == 0) red[t >> 5] = zs;
    __syncthreads();
    if (t == 0) atomicAdd(&g_Z[so*NB + n], red[0] + red[1] + red[2] + red[3]);

    // fea[c] += sum_p V[c][p]*e[p]
    #pragma unroll
    for (int i = 0; i < 8; i++) {
        int c = og*8 + i;
        float fs = 0.f;
        #pragma unroll
        for (int j = 0; j < 8; j++) {
            int pp = pg + 16*j;
            fs = fmaf(Xs[c*TP + pp], es[pp], fs);
        }
        #pragma unroll
        for (int k = 8; k >= 1; k >>= 1) fs += __shfl_xor_sync(0xffffffffu, fs, k);
        if (pg == 0) atomicAdd(&g_fea[(so*NB + n)*CCH + c], fs);
    }
}

// ---------------- gate: fea/Z -> convb -> LN -> sigmoid --------------------
__global__ void k_gate(const float* __restrict__ convb_w,
                       const float* __restrict__ ln_g, const float* __restrict__ ln_b) {
    int so = blockIdx.x, n = blockIdx.y, o = threadIdx.x;
    __shared__ float ff[64], tmp[64];
    int base = (so*NB + n) * CCH;
    float Z = g_Z[so*NB + n];
    ff[o] = g_fea[base + o] / Z;
    __syncthreads();
    float v = 0.f;
    for (int c = 0; c < 64; c++) v = fmaf(ff[c], convb_w[o*64 + c], v);
    float mu = blocksum64(v, tmp) * (1.f/64.f);
    float d = v - mu;
    float var = blocksum64(d*d, tmp) * (1.f/64.f);
    float gz = d * rsqrtf(var + EPSV) * ln_g[o] + ln_b[o];
    g_gate[base + o] = 1.f / (1.f + expf(-gz));
}

// ---------------- pass3: out = gate*half + me ------------------------------
__global__ void k_pass3(const float* __restrict__ xr, const float* __restrict__ xi,
                        float* __restrict__ out) {
    size_t g = (size_t)blockIdx.x * blockDim.x + threadIdx.x;  // float4 index, 16777216 total
    int cl = (int)(g >> 14);          // 0..1023 = s*512 + n*64 + c
    int p4 = (int)(g & 16383);
    int s = cl >> 9, n = (cl >> 6) & 7, c = cl & 63;
    float gate = g_gate[(s*NB + n)*CCH + c];
    float4 h4 = *(const float4*)(g_half + ((size_t)(s*NB + n) << 16) + (size_t)p4*4);
    const float* x = (s == 0 ? xr : xi);
    float4 m4 = *(const float4*)(x + (((size_t)n*64 + c) << 16) + (size_t)p4*4);
    float4 o4;
    o4.x = fmaf(gate, h4.x, m4.x);
    o4.y = fmaf(gate, h4.y, m4.y);
    o4.z = fmaf(gate, h4.z, m4.z);
    o4.w = fmaf(gate, h4.w, m4.w);
    *(float4*)(out + (g << 2)) = o4;
}

// ---------------- launch ---------------------------------------------------
extern "C" void kernel_launch(void* const* d_in, const int* in_sizes, int n_in,
                              void* d_out, int out_size) {
    const float* rgb    = (const float*)d_in[0];
    const float* ir     = (const float*)d_in[1];
    const float* conv_w = (const float*)d_in[2];
    const float* conv_b = (const float*)d_in[3];
    const float* key_w  = (const float*)d_in[4];
    const float* key_g  = (const float*)d_in[5];
    const float* key_b  = (const float*)d_in[6];
    const float* key_m  = (const float*)d_in[7];
    const float* key_v  = (const float*)d_in[8];
    const float* val_w  = (const float*)d_in[9];
    const float* val_g  = (const float*)d_in[10];
    const float* val_b  = (const float*)d_in[11];
    const float* val_m  = (const float*)d_in[12];
    const float* val_v  = (const float*)d_in[13];
    const float* convb_w= (const float*)d_in[14];
    const float* half_w = (const float*)d_in[15];
    const float* half_g = (const float*)d_in[16];
    const float* half_b = (const float*)d_in[17];
    const float* half_m = (const float*)d_in[18];
    const float* half_v = (const float*)d_in[19];
    const float* ln_g   = (const float*)d_in[20];
    const float* ln_b   = (const float*)d_in[21];
    float* out = (float*)d_out;

    const int SMEM1 = (8192 + 4160 + 64 + 32) * 4;
    const int SMEM2 = (8192 + 4160 + 64 + 64 + 64 + 128 + 32) * 4;
    cudaFuncSetAttribute(k_pass1, cudaFuncAttributeMaxDynamicSharedMemorySize, SMEM1);
    cudaFuncSetAttribute(k_pass2, cudaFuncAttributeMaxDynamicSharedMemorySize, SMEM2);

    k_init<<<1, 256>>>(key_w, key_g, key_b, key_m, key_v,
                       val_w, val_g, val_b, val_m, val_v,
                       half_w, half_g, half_b, half_m, half_v);
    dim3 gP(HW / TP, NB, 2);
    k_pass1<<<gP, 128, SMEM1>>>(rgb, ir, conv_w);
    k_mid<<<dim3(2, NB), 64>>>(conv_w, conv_b);
    k_pass2<<<gP, 128, SMEM2>>>(rgb, ir);
    k_gate<<<dim3(2, NB), 64>>>(convb_w, ln_g, ln_b);
    k_pass3<<<65536, 256>>>(rgb, ir, out);
}